// round 1
// baseline (speedup 1.0000x reference)
#include <cuda_runtime.h>
#include <cuda_bf16.h>
#include <stdint.h>

#define TPB   512
#define NNODE 49
#define PADN  64
#define BT    2
#define MROWS 128
#define DIM   768
#define C1    256
#define C2    128
#define NCLS  13
#define KT    16
#define NKT1  48
#define NKT2  16

// smem strides (elements)
#define SA  18    // A tile row stride (bf16)
#define SB  18    // B tile row stride, transposed [n][k] (bf16)
#define SH  264   // H1 row stride (bf16)  -> 132 words, %32==4 -> conflict-free frag loads
#define ST1 68    // T1 chunk row stride (float)
#define ST2 132   // T2 row stride (float)

// smem byte offsets
#define OFF_AHI   0
#define OFF_ALO   4608
#define OFF_BHI   9216
#define OFF_BLO   18432
#define OFF_T1C   27648
#define OFF_H1HI  62464      // also aliased as T2 (float [128][132]) after GEMM2
#define OFF_H1LO  130048
#define OFF_ADJW  197632
#define OFF_ADJI  199424
#define OFF_DINV  201216
#define OFF_POOL  201472
#define SMEM_BYTES 202496

__device__ __forceinline__ void mma_bf16(float* c, const unsigned* a, const unsigned* b) {
    asm volatile(
        "mma.sync.aligned.m16n8k16.row.col.f32.bf16.bf16.f32 "
        "{%0,%1,%2,%3}, {%4,%5,%6,%7}, {%8,%9}, {%0,%1,%2,%3};\n"
        : "+f"(c[0]), "+f"(c[1]), "+f"(c[2]), "+f"(c[3])
        : "r"(a[0]), "r"(a[1]), "r"(a[2]), "r"(a[3]), "r"(b[0]), "r"(b[1]));
}

// split two floats into packed (hi,hi) and (lo,lo) bf16x2 words (elem0 in low half)
__device__ __forceinline__ void split2(float a, float b, unsigned& hi, unsigned& lo) {
    __nv_bfloat16 ah = __float2bfloat16(a), bh = __float2bfloat16(b);
    float ar = a - __bfloat162float(ah);
    float br = b - __bfloat162float(bh);
    __nv_bfloat16 al = __float2bfloat16(ar), bl = __float2bfloat16(br);
    hi = ((unsigned)__bfloat16_as_ushort(bh) << 16) | (unsigned)__bfloat16_as_ushort(ah);
    lo = ((unsigned)__bfloat16_as_ushort(bl) << 16) | (unsigned)__bfloat16_as_ushort(al);
}

__global__ void __launch_bounds__(TPB, 1)
gnn_fused(const float* __restrict__ x,  const float* __restrict__ W1,
          const float* __restrict__ b1, const float* __restrict__ W2,
          const float* __restrict__ b2, const float* __restrict__ Wf,
          const float* __restrict__ bf, float* __restrict__ out)
{
    extern __shared__ unsigned char smem[];
    __nv_bfloat16* Ahi  = (__nv_bfloat16*)(smem + OFF_AHI);
    __nv_bfloat16* Alo  = (__nv_bfloat16*)(smem + OFF_ALO);
    __nv_bfloat16* Bhi  = (__nv_bfloat16*)(smem + OFF_BHI);
    __nv_bfloat16* Blo  = (__nv_bfloat16*)(smem + OFF_BLO);
    float*         T1c  = (float*)(smem + OFF_T1C);
    __nv_bfloat16* H1hi = (__nv_bfloat16*)(smem + OFF_H1HI);
    __nv_bfloat16* H1lo = (__nv_bfloat16*)(smem + OFF_H1LO);
    float*         adjw = (float*)(smem + OFF_ADJW);
    int*           adji = (int*)(smem + OFF_ADJI);
    float*         dinv = (float*)(smem + OFF_DINV);
    float*         pooled = (float*)(smem + OFF_POOL);

    const int tid  = threadIdx.x;
    const int lane = tid & 31;
    const int wid  = tid >> 5;
    const int wm   = wid >> 1;   // 0..7  (m16 tile row)
    const int wn   = wid & 1;    // 0..1  (n128 half for GEMM1, n64 half for GEMM2)
    const int tr   = lane >> 2;
    const int tc   = lane & 3;
    const int b0   = blockIdx.x * BT;

    // ---- build normalized adjacency (exact fp32, sparse, <=9 nbrs) ----
    if (tid < NNODE) {
        int r = tid / 7, c = tid % 7;
        int nr = min(r + 1, 6) - max(r - 1, 0) + 1;
        int nc = min(c + 1, 6) - max(c - 1, 0) + 1;
        dinv[tid] = 1.0f / sqrtf((float)(nr * nc));
    }
    __syncthreads();
    if (tid < NNODE) {
        int r = tid / 7, c = tid % 7;
        float di = dinv[tid];
        int t = 0;
        for (int dr = -1; dr <= 1; dr++)
            for (int dc = -1; dc <= 1; dc++) {
                int rr = r + dr, cc = c + dc;
                if (rr >= 0 && rr < 7 && cc >= 0 && cc < 7) {
                    int j = rr * 7 + cc;
                    adji[tid * 9 + t] = j;
                    adjw[tid * 9 + t] = di * dinv[j];
                    t++;
                }
            }
        for (; t < 9; t++) { adji[tid * 9 + t] = 0; adjw[tid * 9 + t] = 0.0f; }
    }

    // =========== GEMM1: T1 = X @ W1   (128 x 256 x 768, bf16x3) ===========
    float acc[16][4];
    #pragma unroll
    for (int j = 0; j < 16; j++)
        #pragma unroll
        for (int k = 0; k < 4; k++) acc[j][k] = 0.0f;

    const int arow  = tid >> 2;          // 0..127
    const int aquad = tid & 3;           // 0..3 (float4 within 16-wide k tile)
    const int ag    = arow >> 6;
    const int anode = arow & 63;
    const bool avalid = (anode < NNODE);
    const float* aptr = x + ((size_t)(b0 + ag) * NNODE + anode) * DIM + aquad * 4;

    const int bk0 = tid >> 6,        bn0 = (tid & 63) * 4;
    const int f1  = tid + TPB;
    const int bk1 = f1 >> 6,         bn1 = (f1 & 63) * 4;

    float4 aReg  = avalid ? *(const float4*)(aptr) : make_float4(0.f, 0.f, 0.f, 0.f);
    float4 bReg0 = *(const float4*)(W1 + (size_t)bk0 * C1 + bn0);
    float4 bReg1 = *(const float4*)(W1 + (size_t)bk1 * C1 + bn1);

    // store tile kt=0
    {
        unsigned h01, l01, h23, l23;
        split2(aReg.x, aReg.y, h01, l01);
        split2(aReg.z, aReg.w, h23, l23);
        unsigned* pA = (unsigned*)(Ahi + arow * SA + aquad * 4);
        pA[0] = h01; pA[1] = h23;
        unsigned* pL = (unsigned*)(Alo + arow * SA + aquad * 4);
        pL[0] = l01; pL[1] = l23;
        float v0[4] = { bReg0.x, bReg0.y, bReg0.z, bReg0.w };
        float v1[4] = { bReg1.x, bReg1.y, bReg1.z, bReg1.w };
        #pragma unroll
        for (int j = 0; j < 4; j++) {
            __nv_bfloat16 h = __float2bfloat16(v0[j]);
            Bhi[(bn0 + j) * SB + bk0] = h;
            Blo[(bn0 + j) * SB + bk0] = __float2bfloat16(v0[j] - __bfloat162float(h));
            __nv_bfloat16 g = __float2bfloat16(v1[j]);
            Bhi[(bn1 + j) * SB + bk1] = g;
            Blo[(bn1 + j) * SB + bk1] = __float2bfloat16(v1[j] - __bfloat162float(g));
        }
    }
    __syncthreads();

    #pragma unroll 1
    for (int kt = 0; kt < NKT1; kt++) {
        const bool more = (kt + 1 < NKT1);
        if (more) {
            aReg  = avalid ? *(const float4*)(aptr + (size_t)(kt + 1) * KT)
                           : make_float4(0.f, 0.f, 0.f, 0.f);
            bReg0 = *(const float4*)(W1 + (size_t)((kt + 1) * KT + bk0) * C1 + bn0);
            bReg1 = *(const float4*)(W1 + (size_t)((kt + 1) * KT + bk1) * C1 + bn1);
        }
        // A fragments (one m16 tile per warp)
        unsigned afh[4], afl[4];
        {
            const int row = wm * 16 + tr;
            const __nv_bfloat16* p = Ahi + row * SA + tc * 2;
            afh[0] = *(const unsigned*)(p);
            afh[1] = *(const unsigned*)(p + 8 * SA);
            afh[2] = *(const unsigned*)(p + 8);
            afh[3] = *(const unsigned*)(p + 8 * SA + 8);
            const __nv_bfloat16* q = Alo + row * SA + tc * 2;
            afl[0] = *(const unsigned*)(q);
            afl[1] = *(const unsigned*)(q + 8 * SA);
            afl[2] = *(const unsigned*)(q + 8);
            afl[3] = *(const unsigned*)(q + 8 * SA + 8);
        }
        #pragma unroll
        for (int nj = 0; nj < 16; nj++) {
            const int n = wn * 128 + nj * 8 + tr;
            const __nv_bfloat16* pb = Bhi + n * SB + tc * 2;
            unsigned bh[2] = { *(const unsigned*)(pb), *(const unsigned*)(pb + 8) };
            const __nv_bfloat16* ql = Blo + n * SB + tc * 2;
            unsigned bl[2] = { *(const unsigned*)(ql), *(const unsigned*)(ql + 8) };
            mma_bf16(acc[nj], afh, bh);
            mma_bf16(acc[nj], afh, bl);
            mma_bf16(acc[nj], afl, bh);
        }
        __syncthreads();
        if (more) {
            unsigned h01, l01, h23, l23;
            split2(aReg.x, aReg.y, h01, l01);
            split2(aReg.z, aReg.w, h23, l23);
            unsigned* pA = (unsigned*)(Ahi + arow * SA + aquad * 4);
            pA[0] = h01; pA[1] = h23;
            unsigned* pL = (unsigned*)(Alo + arow * SA + aquad * 4);
            pL[0] = l01; pL[1] = l23;
            float v0[4] = { bReg0.x, bReg0.y, bReg0.z, bReg0.w };
            float v1[4] = { bReg1.x, bReg1.y, bReg1.z, bReg1.w };
            #pragma unroll
            for (int j = 0; j < 4; j++) {
                __nv_bfloat16 h = __float2bfloat16(v0[j]);
                Bhi[(bn0 + j) * SB + bk0] = h;
                Blo[(bn0 + j) * SB + bk0] = __float2bfloat16(v0[j] - __bfloat162float(h));
                __nv_bfloat16 g = __float2bfloat16(v1[j]);
                Bhi[(bn1 + j) * SB + bk1] = g;
                Blo[(bn1 + j) * SB + bk1] = __float2bfloat16(v1[j] - __bfloat162float(g));
            }
        }
        __syncthreads();
    }

    // ===== epilogue 1 (chunked): H1 = relu(ADJ @ T1 + b1), split to bf16 hi/lo =====
    #pragma unroll 1
    for (int ci = 0; ci < 4; ci++) {
        __syncthreads();
        if ((ci >> 1) == wn) {
            const int njb = (ci & 1) * 8;
            #pragma unroll
            for (int nj2 = 0; nj2 < 8; nj2++) {
                const int nj  = njb + nj2;
                const int row = wm * 16 + tr;
                const int col = nj2 * 8 + tc * 2;
                T1c[row * ST1 + col]           = acc[nj][0];
                T1c[row * ST1 + col + 1]       = acc[nj][1];
                T1c[(row + 8) * ST1 + col]     = acc[nj][2];
                T1c[(row + 8) * ST1 + col + 1] = acc[nj][3];
            }
        }
        __syncthreads();
        for (int task = tid; task < 2 * NNODE * 64; task += TPB) {
            const int cl   = task & 63;
            const int rest = task >> 6;                  // 0..97
            const int g    = (rest >= NNODE) ? 1 : 0;
            const int i    = rest - g * NNODE;
            const int cg   = ci * 64 + cl;
            float s = b1[cg];
            #pragma unroll
            for (int t = 0; t < 9; t++)
                s += adjw[i * 9 + t] * T1c[(g * PADN + adji[i * 9 + t]) * ST1 + cl];
            s = fmaxf(s, 0.0f);
            __nv_bfloat16 h = __float2bfloat16(s);
            H1hi[(g * PADN + i) * SH + cg] = h;
            H1lo[(g * PADN + i) * SH + cg] = __float2bfloat16(s - __bfloat162float(h));
        }
    }

    // =========== GEMM2: T2 = H1 @ W2   (128 x 128 x 256, bf16x3) ===========
    #pragma unroll
    for (int j = 0; j < 8; j++)
        #pragma unroll
        for (int k = 0; k < 4; k++) acc[j][k] = 0.0f;

    const int ck = tid >> 5;            // 0..15
    const int cn = (tid & 31) * 4;      // 0..124
    float4 c2reg = *(const float4*)(W2 + (size_t)ck * C2 + cn);
    __syncthreads();
    {
        float v[4] = { c2reg.x, c2reg.y, c2reg.z, c2reg.w };
        #pragma unroll
        for (int j = 0; j < 4; j++) {
            __nv_bfloat16 h = __float2bfloat16(v[j]);
            Bhi[(cn + j) * SB + ck] = h;
            Blo[(cn + j) * SB + ck] = __float2bfloat16(v[j] - __bfloat162float(h));
        }
    }
    __syncthreads();

    #pragma unroll 1
    for (int kt = 0; kt < NKT2; kt++) {
        const bool more = (kt + 1 < NKT2);
        if (more) c2reg = *(const float4*)(W2 + (size_t)((kt + 1) * KT + ck) * C2 + cn);
        unsigned afh[4], afl[4];
        {
            const int row = wm * 16 + tr;
            const __nv_bfloat16* p = H1hi + row * SH + kt * KT + tc * 2;
            afh[0] = *(const unsigned*)(p);
            afh[1] = *(const unsigned*)(p + 8 * SH);
            afh[2] = *(const unsigned*)(p + 8);
            afh[3] = *(const unsigned*)(p + 8 * SH + 8);
            const __nv_bfloat16* q = H1lo + row * SH + kt * KT + tc * 2;
            afl[0] = *(const unsigned*)(q);
            afl[1] = *(const unsigned*)(q + 8 * SH);
            afl[2] = *(const unsigned*)(q + 8);
            afl[3] = *(const unsigned*)(q + 8 * SH + 8);
        }
        #pragma unroll
        for (int nj = 0; nj < 8; nj++) {
            const int n = wn * 64 + nj * 8 + tr;
            const __nv_bfloat16* pb = Bhi + n * SB + tc * 2;
            unsigned bh[2] = { *(const unsigned*)(pb), *(const unsigned*)(pb + 8) };
            const __nv_bfloat16* ql = Blo + n * SB + tc * 2;
            unsigned bl[2] = { *(const unsigned*)(ql), *(const unsigned*)(ql + 8) };
            mma_bf16(acc[nj], afh, bh);
            mma_bf16(acc[nj], afh, bl);
            mma_bf16(acc[nj], afl, bh);
        }
        __syncthreads();
        if (more) {
            float v[4] = { c2reg.x, c2reg.y, c2reg.z, c2reg.w };
            #pragma unroll
            for (int j = 0; j < 4; j++) {
                __nv_bfloat16 h = __float2bfloat16(v[j]);
                Bhi[(cn + j) * SB + ck] = h;
                Blo[(cn + j) * SB + ck] = __float2bfloat16(v[j] - __bfloat162float(h));
            }
        }
        __syncthreads();
    }

    // ===== epilogue 2: T2 -> ADJ + bias + relu + mean pool -> head =====
    float* T2 = (float*)(smem + OFF_H1HI);   // alias: H1hi no longer needed
    #pragma unroll
    for (int nj = 0; nj < 8; nj++) {
        const int row = wm * 16 + tr;
        const int col = wn * 64 + nj * 8 + tc * 2;
        T2[row * ST2 + col]           = acc[nj][0];
        T2[row * ST2 + col + 1]       = acc[nj][1];
        T2[(row + 8) * ST2 + col]     = acc[nj][2];
        T2[(row + 8) * ST2 + col + 1] = acc[nj][3];
    }
    __syncthreads();

    if (tid < BT * C2) {
        const int g = tid >> 7, c = tid & 127;
        const float bias = b2[c];
        float ps = 0.0f;
        for (int i = 0; i < NNODE; i++) {
            float s = bias;
            #pragma unroll
            for (int t = 0; t < 9; t++)
                s += adjw[i * 9 + t] * T2[(g * PADN + adji[i * 9 + t]) * ST2 + c];
            ps += fmaxf(s, 0.0f);
        }
        pooled[tid] = ps / 49.0f;
    }
    __syncthreads();

    if (tid < BT * NCLS) {
        const int g = tid / NCLS, o = tid - g * NCLS;
        float s = bf[o];
        const float* pp = pooled + g * C2;
        #pragma unroll 8
        for (int k = 0; k < C2; k++) s += pp[k] * Wf[k * NCLS + o];
        out[(size_t)(b0 + g) * NCLS + o] = s;
    }
}

extern "C" void kernel_launch(void* const* d_in, const int* in_sizes, int n_in,
                              void* d_out, int out_size)
{
    const float* x  = (const float*)d_in[0];
    const float* W1 = (const float*)d_in[1];
    const float* b1 = (const float*)d_in[2];
    const float* W2 = (const float*)d_in[3];
    const float* b2 = (const float*)d_in[4];
    const float* Wf = (const float*)d_in[5];
    const float* bf = (const float*)d_in[6];
    float* out = (float*)d_out;

    const int B = in_sizes[0] / (NNODE * DIM);   // 4096
    cudaFuncSetAttribute(gnn_fused, cudaFuncAttributeMaxDynamicSharedMemorySize, SMEM_BYTES);
    gnn_fused<<<B / BT, TPB, SMEM_BYTES>>>(x, W1, b1, W2, b2, Wf, bf, out);
}

// round 2
// speedup vs baseline: 1.0028x; 1.0028x over previous
#include <cuda_runtime.h>
#include <cuda_bf16.h>
#include <stdint.h>

#define TPB   512
#define NNODE 49
#define PADN  64
#define BT    2
#define MROWS 128
#define DIM   768
#define C1    256
#define C2    128
#define NCLS  13
#define KT    16
#define NKT1  48
#define NKT2  16

// smem strides (elements)
#define SA  18    // A tile row stride (bf16)
#define SB  18    // B tile row stride, transposed [n][k] (bf16)
#define SH  264   // H1 row stride (bf16)  -> 132 words, %32==4 -> conflict-free frag loads
#define ST1 68    // T1 chunk row stride (float)
#define ST2 132   // T2 row stride (float)

// smem byte offsets
#define OFF_AHI   0
#define OFF_ALO   4608
#define OFF_BHI   9216
#define OFF_BLO   18432
#define OFF_T1C   27648
#define OFF_H1HI  62464      // also aliased as T2 (float [128][132]) after GEMM2
#define OFF_H1LO  130048
#define OFF_ADJW  197632
#define OFF_ADJI  199424
#define OFF_DINV  201216
#define OFF_POOL  201472
#define SMEM_BYTES 202496

__device__ __forceinline__ void mma_bf16(float* c, const unsigned* a, const unsigned* b) {
    asm volatile(
        "mma.sync.aligned.m16n8k16.row.col.f32.bf16.bf16.f32 "
        "{%0,%1,%2,%3}, {%4,%5,%6,%7}, {%8,%9}, {%0,%1,%2,%3};\n"
        : "+f"(c[0]), "+f"(c[1]), "+f"(c[2]), "+f"(c[3])
        : "r"(a[0]), "r"(a[1]), "r"(a[2]), "r"(a[3]), "r"(b[0]), "r"(b[1]));
}

// split two floats into packed (hi,hi) and (lo,lo) bf16x2 words (elem0 in low half)
__device__ __forceinline__ void split2(float a, float b, unsigned& hi, unsigned& lo) {
    __nv_bfloat16 ah = __float2bfloat16(a), bh = __float2bfloat16(b);
    float ar = a - __bfloat162float(ah);
    float br = b - __bfloat162float(bh);
    __nv_bfloat16 al = __float2bfloat16(ar), bl = __float2bfloat16(br);
    hi = ((unsigned)__bfloat16_as_ushort(bh) << 16) | (unsigned)__bfloat16_as_ushort(ah);
    lo = ((unsigned)__bfloat16_as_ushort(bl) << 16) | (unsigned)__bfloat16_as_ushort(al);
}

__global__ void __launch_bounds__(TPB, 1)
gnn_fused(const float* __restrict__ x,  const float* __restrict__ W1,
          const float* __restrict__ b1, const float* __restrict__ W2,
          const float* __restrict__ b2, const float* __restrict__ Wf,
          const float* __restrict__ bf, float* __restrict__ out)
{
    extern __shared__ unsigned char smem[];
    __nv_bfloat16* Ahi  = (__nv_bfloat16*)(smem + OFF_AHI);
    __nv_bfloat16* Alo  = (__nv_bfloat16*)(smem + OFF_ALO);
    __nv_bfloat16* Bhi  = (__nv_bfloat16*)(smem + OFF_BHI);
    __nv_bfloat16* Blo  = (__nv_bfloat16*)(smem + OFF_BLO);
    float*         T1c  = (float*)(smem + OFF_T1C);
    __nv_bfloat16* H1hi = (__nv_bfloat16*)(smem + OFF_H1HI);
    __nv_bfloat16* H1lo = (__nv_bfloat16*)(smem + OFF_H1LO);
    float*         adjw = (float*)(smem + OFF_ADJW);
    int*           adji = (int*)(smem + OFF_ADJI);
    float*         dinv = (float*)(smem + OFF_DINV);
    float*         pooled = (float*)(smem + OFF_POOL);

    const int tid  = threadIdx.x;
    const int lane = tid & 31;
    const int wid  = tid >> 5;
    const int wm   = wid >> 1;   // 0..7  (m16 tile row)
    const int wn   = wid & 1;    // 0..1  (n128 half for GEMM1, n64 half for GEMM2)
    const int tr   = lane >> 2;
    const int tc   = lane & 3;
    const int b0   = blockIdx.x * BT;

    // ---- build normalized adjacency (exact fp32, sparse, <=9 nbrs) ----
    if (tid < NNODE) {
        int r = tid / 7, c = tid % 7;
        int nr = min(r + 1, 6) - max(r - 1, 0) + 1;
        int nc = min(c + 1, 6) - max(c - 1, 0) + 1;
        dinv[tid] = 1.0f / sqrtf((float)(nr * nc));
    }
    __syncthreads();
    if (tid < NNODE) {
        int r = tid / 7, c = tid % 7;
        float di = dinv[tid];
        int t = 0;
        for (int dr = -1; dr <= 1; dr++)
            for (int dc = -1; dc <= 1; dc++) {
                int rr = r + dr, cc = c + dc;
                if (rr >= 0 && rr < 7 && cc >= 0 && cc < 7) {
                    int j = rr * 7 + cc;
                    adji[tid * 9 + t] = j;
                    adjw[tid * 9 + t] = di * dinv[j];
                    t++;
                }
            }
        for (; t < 9; t++) { adji[tid * 9 + t] = 0; adjw[tid * 9 + t] = 0.0f; }
    }

    // =========== GEMM1: T1 = X @ W1   (128 x 256 x 768, bf16x3) ===========
    float acc[16][4];
    #pragma unroll
    for (int j = 0; j < 16; j++)
        #pragma unroll
        for (int k = 0; k < 4; k++) acc[j][k] = 0.0f;

    const int arow  = tid >> 2;          // 0..127
    const int aquad = tid & 3;           // 0..3 (float4 within 16-wide k tile)
    const int ag    = arow >> 6;
    const int anode = arow & 63;
    const bool avalid = (anode < NNODE);
    const float* aptr = x + ((size_t)(b0 + ag) * NNODE + anode) * DIM + aquad * 4;

    const int bk0 = tid >> 6,        bn0 = (tid & 63) * 4;
    const int f1  = tid + TPB;
    const int bk1 = f1 >> 6,         bn1 = (f1 & 63) * 4;

    float4 aReg  = avalid ? *(const float4*)(aptr) : make_float4(0.f, 0.f, 0.f, 0.f);
    float4 bReg0 = *(const float4*)(W1 + (size_t)bk0 * C1 + bn0);
    float4 bReg1 = *(const float4*)(W1 + (size_t)bk1 * C1 + bn1);

    // store tile kt=0
    {
        unsigned h01, l01, h23, l23;
        split2(aReg.x, aReg.y, h01, l01);
        split2(aReg.z, aReg.w, h23, l23);
        unsigned* pA = (unsigned*)(Ahi + arow * SA + aquad * 4);
        pA[0] = h01; pA[1] = h23;
        unsigned* pL = (unsigned*)(Alo + arow * SA + aquad * 4);
        pL[0] = l01; pL[1] = l23;
        float v0[4] = { bReg0.x, bReg0.y, bReg0.z, bReg0.w };
        float v1[4] = { bReg1.x, bReg1.y, bReg1.z, bReg1.w };
        #pragma unroll
        for (int j = 0; j < 4; j++) {
            __nv_bfloat16 h = __float2bfloat16(v0[j]);
            Bhi[(bn0 + j) * SB + bk0] = h;
            Blo[(bn0 + j) * SB + bk0] = __float2bfloat16(v0[j] - __bfloat162float(h));
            __nv_bfloat16 g = __float2bfloat16(v1[j]);
            Bhi[(bn1 + j) * SB + bk1] = g;
            Blo[(bn1 + j) * SB + bk1] = __float2bfloat16(v1[j] - __bfloat162float(g));
        }
    }
    __syncthreads();

    #pragma unroll 1
    for (int kt = 0; kt < NKT1; kt++) {
        const bool more = (kt + 1 < NKT1);
        if (more) {
            aReg  = avalid ? *(const float4*)(aptr + (size_t)(kt + 1) * KT)
                           : make_float4(0.f, 0.f, 0.f, 0.f);
            bReg0 = *(const float4*)(W1 + (size_t)((kt + 1) * KT + bk0) * C1 + bn0);
            bReg1 = *(const float4*)(W1 + (size_t)((kt + 1) * KT + bk1) * C1 + bn1);
        }
        // A fragments (one m16 tile per warp)
        unsigned afh[4], afl[4];
        {
            const int row = wm * 16 + tr;
            const __nv_bfloat16* p = Ahi + row * SA + tc * 2;
            afh[0] = *(const unsigned*)(p);
            afh[1] = *(const unsigned*)(p + 8 * SA);
            afh[2] = *(const unsigned*)(p + 8);
            afh[3] = *(const unsigned*)(p + 8 * SA + 8);
            const __nv_bfloat16* q = Alo + row * SA + tc * 2;
            afl[0] = *(const unsigned*)(q);
            afl[1] = *(const unsigned*)(q + 8 * SA);
            afl[2] = *(const unsigned*)(q + 8);
            afl[3] = *(const unsigned*)(q + 8 * SA + 8);
        }
        #pragma unroll
        for (int nj = 0; nj < 16; nj++) {
            const int n = wn * 128 + nj * 8 + tr;
            const __nv_bfloat16* pb = Bhi + n * SB + tc * 2;
            unsigned bh[2] = { *(const unsigned*)(pb), *(const unsigned*)(pb + 8) };
            const __nv_bfloat16* ql = Blo + n * SB + tc * 2;
            unsigned bl[2] = { *(const unsigned*)(ql), *(const unsigned*)(ql + 8) };
            mma_bf16(acc[nj], afh, bh);
            mma_bf16(acc[nj], afh, bl);
            mma_bf16(acc[nj], afl, bh);
        }
        __syncthreads();
        if (more) {
            unsigned h01, l01, h23, l23;
            split2(aReg.x, aReg.y, h01, l01);
            split2(aReg.z, aReg.w, h23, l23);
            unsigned* pA = (unsigned*)(Ahi + arow * SA + aquad * 4);
            pA[0] = h01; pA[1] = h23;
            unsigned* pL = (unsigned*)(Alo + arow * SA + aquad * 4);
            pL[0] = l01; pL[1] = l23;
            float v0[4] = { bReg0.x, bReg0.y, bReg0.z, bReg0.w };
            float v1[4] = { bReg1.x, bReg1.y, bReg1.z, bReg1.w };
            #pragma unroll
            for (int j = 0; j < 4; j++) {
                __nv_bfloat16 h = __float2bfloat16(v0[j]);
                Bhi[(bn0 + j) * SB + bk0] = h;
                Blo[(bn0 + j) * SB + bk0] = __float2bfloat16(v0[j] - __bfloat162float(h));
                __nv_bfloat16 g = __float2bfloat16(v1[j]);
                Bhi[(bn1 + j) * SB + bk1] = g;
                Blo[(bn1 + j) * SB + bk1] = __float2bfloat16(v1[j] - __bfloat162float(g));
            }
        }
        __syncthreads();
    }

    // ===== epilogue 1 (chunked): H1 = relu(ADJ @ T1 + b1), split to bf16 hi/lo =====
    #pragma unroll 1
    for (int ci = 0; ci < 4; ci++) {
        __syncthreads();
        if ((ci >> 1) == wn) {
            const int njb = (ci & 1) * 8;
            #pragma unroll
            for (int nj2 = 0; nj2 < 8; nj2++) {
                const int nj  = njb + nj2;
                const int row = wm * 16 + tr;
                const int col = nj2 * 8 + tc * 2;
                T1c[row * ST1 + col]           = acc[nj][0];
                T1c[row * ST1 + col + 1]       = acc[nj][1];
                T1c[(row + 8) * ST1 + col]     = acc[nj][2];
                T1c[(row + 8) * ST1 + col + 1] = acc[nj][3];
            }
        }
        __syncthreads();
        for (int task = tid; task < 2 * NNODE * 64; task += TPB) {
            const int cl   = task & 63;
            const int rest = task >> 6;                  // 0..97
            const int g    = (rest >= NNODE) ? 1 : 0;
            const int i    = rest - g * NNODE;
            const int cg   = ci * 64 + cl;
            float s = b1[cg];
            #pragma unroll
            for (int t = 0; t < 9; t++)
                s += adjw[i * 9 + t] * T1c[(g * PADN + adji[i * 9 + t]) * ST1 + cl];
            s = fmaxf(s, 0.0f);
            __nv_bfloat16 h = __float2bfloat16(s);
            H1hi[(g * PADN + i) * SH + cg] = h;
            H1lo[(g * PADN + i) * SH + cg] = __float2bfloat16(s - __bfloat162float(h));
        }
    }

    // =========== GEMM2: T2 = H1 @ W2   (128 x 128 x 256, bf16x3) ===========
    #pragma unroll
    for (int j = 0; j < 8; j++)
        #pragma unroll
        for (int k = 0; k < 4; k++) acc[j][k] = 0.0f;

    const int ck = tid >> 5;            // 0..15
    const int cn = (tid & 31) * 4;      // 0..124
    float4 c2reg = *(const float4*)(W2 + (size_t)ck * C2 + cn);
    __syncthreads();
    {
        float v[4] = { c2reg.x, c2reg.y, c2reg.z, c2reg.w };
        #pragma unroll
        for (int j = 0; j < 4; j++) {
            __nv_bfloat16 h = __float2bfloat16(v[j]);
            Bhi[(cn + j) * SB + ck] = h;
            Blo[(cn + j) * SB + ck] = __float2bfloat16(v[j] - __bfloat162float(h));
        }
    }
    __syncthreads();

    #pragma unroll 1
    for (int kt = 0; kt < NKT2; kt++) {
        const bool more = (kt + 1 < NKT2);
        if (more) c2reg = *(const float4*)(W2 + (size_t)((kt + 1) * KT + ck) * C2 + cn);
        unsigned afh[4], afl[4];
        {
            const int row = wm * 16 + tr;
            const __nv_bfloat16* p = H1hi + row * SH + kt * KT + tc * 2;
            afh[0] = *(const unsigned*)(p);
            afh[1] = *(const unsigned*)(p + 8 * SH);
            afh[2] = *(const unsigned*)(p + 8);
            afh[3] = *(const unsigned*)(p + 8 * SH + 8);
            const __nv_bfloat16* q = H1lo + row * SH + kt * KT + tc * 2;
            afl[0] = *(const unsigned*)(q);
            afl[1] = *(const unsigned*)(q + 8 * SH);
            afl[2] = *(const unsigned*)(q + 8);
            afl[3] = *(const unsigned*)(q + 8 * SH + 8);
        }
        #pragma unroll
        for (int nj = 0; nj < 8; nj++) {
            const int n = wn * 64 + nj * 8 + tr;
            const __nv_bfloat16* pb = Bhi + n * SB + tc * 2;
            unsigned bh[2] = { *(const unsigned*)(pb), *(const unsigned*)(pb + 8) };
            const __nv_bfloat16* ql = Blo + n * SB + tc * 2;
            unsigned bl[2] = { *(const unsigned*)(ql), *(const unsigned*)(ql + 8) };
            mma_bf16(acc[nj], afh, bh);
            mma_bf16(acc[nj], afh, bl);
            mma_bf16(acc[nj], afl, bh);
        }
        __syncthreads();
        if (more) {
            float v[4] = { c2reg.x, c2reg.y, c2reg.z, c2reg.w };
            #pragma unroll
            for (int j = 0; j < 4; j++) {
                __nv_bfloat16 h = __float2bfloat16(v[j]);
                Bhi[(cn + j) * SB + ck] = h;
                Blo[(cn + j) * SB + ck] = __float2bfloat16(v[j] - __bfloat162float(h));
            }
        }
        __syncthreads();
    }

    // ===== epilogue 2: T2 -> ADJ + bias + relu + mean pool -> head =====
    float* T2 = (float*)(smem + OFF_H1HI);   // alias: H1hi no longer needed
    #pragma unroll
    for (int nj = 0; nj < 8; nj++) {
        const int row = wm * 16 + tr;
        const int col = wn * 64 + nj * 8 + tc * 2;
        T2[row * ST2 + col]           = acc[nj][0];
        T2[row * ST2 + col + 1]       = acc[nj][1];
        T2[(row + 8) * ST2 + col]     = acc[nj][2];
        T2[(row + 8) * ST2 + col + 1] = acc[nj][3];
    }
    __syncthreads();

    if (tid < BT * C2) {
        const int g = tid >> 7, c = tid & 127;
        const float bias = b2[c];
        float ps = 0.0f;
        for (int i = 0; i < NNODE; i++) {
            float s = bias;
            #pragma unroll
            for (int t = 0; t < 9; t++)
                s += adjw[i * 9 + t] * T2[(g * PADN + adji[i * 9 + t]) * ST2 + c];
            ps += fmaxf(s, 0.0f);
        }
        pooled[tid] = ps / 49.0f;
    }
    __syncthreads();

    if (tid < BT * NCLS) {
        const int g = tid / NCLS, o = tid - g * NCLS;
        float s = bf[o];
        const float* pp = pooled + g * C2;
        #pragma unroll 8
        for (int k = 0; k < C2; k++) s += pp[k] * Wf[k * NCLS + o];
        out[(size_t)(b0 + g) * NCLS + o] = s;
    }
}

extern "C" void kernel_launch(void* const* d_in, const int* in_sizes, int n_in,
                              void* d_out, int out_size)
{
    const float* x  = (const float*)d_in[0];
    const float* W1 = (const float*)d_in[1];
    const float* b1 = (const float*)d_in[2];
    const float* W2 = (const float*)d_in[3];
    const float* b2 = (const float*)d_in[4];
    const float* Wf = (const float*)d_in[5];
    const float* bf = (const float*)d_in[6];
    float* out = (float*)d_out;

    const int B = in_sizes[0] / (NNODE * DIM);   // 4096
    cudaFuncSetAttribute(gnn_fused, cudaFuncAttributeMaxDynamicSharedMemorySize, SMEM_BYTES);
    gnn_fused<<<B / BT, TPB, SMEM_BYTES>>>(x, W1, b1, W2, b2, Wf, bf, out);
}